// round 12
// baseline (speedup 1.0000x reference)
#include <cuda_runtime.h>
#include <cuda_bf16.h>
#include <cstdint>

#define B_DIM 4096
#define IN_DIM 2048
#define F_DIM 4096

// ---------------------------------------------------------------------------
// Scratch (device globals: no allocation allowed)
// ---------------------------------------------------------------------------
__device__ float          g_xr[B_DIM * IN_DIM];    // rotated activations (fp32 — REQUIRED)
__device__ float          g_wr[IN_DIM * F_DIM];    // rotated weights (fp32 — REQUIRED)
__device__ __nv_bfloat16  g_xq[B_DIM * IN_DIM];    // quantized activations [M][K]
__device__ __nv_bfloat16  g_wqT[F_DIM * IN_DIM];   // quantized weights TRANSPOSED [N][K]
__device__ float          g_yr[B_DIM * F_DIM];     // GEMM result (float, exact ints)
__device__ int            g_maxx_bits;
__device__ int            g_maxw_bits;

// ===========================================================================
// Helpers
// ===========================================================================
__device__ __forceinline__ uint32_t smem_u32(const void* p) {
    uint32_t a;
    asm("{ .reg .u64 t; cvta.to.shared.u64 t, %1; cvt.u32.u64 %0, t; }" : "=r"(a) : "l"(p));
    return a;
}

__device__ __forceinline__ void cpasync16(uint32_t dst, const void* src) {
    asm volatile("cp.async.cg.shared.global [%0], [%1], 16;\n" :: "r"(dst), "l"(src));
}

// Swizzle<3,4,3>: XOR 16B-chunk bits [6:4] with 128B-line bits [9:7]
__device__ __forceinline__ uint32_t swz(uint32_t o) { return o ^ (((o >> 7) & 7) << 4); }

__device__ __forceinline__ void ldsm_x4(uint32_t r[4], uint32_t addr) {
    asm volatile("ldmatrix.sync.aligned.m8n8.x4.shared.b16 {%0,%1,%2,%3}, [%4];"
                 : "=r"(r[0]), "=r"(r[1]), "=r"(r[2]), "=r"(r[3]) : "r"(addr));
}

__device__ __forceinline__ void mma_bf16(float c[4], const uint32_t a[4], uint32_t b0, uint32_t b1) {
    asm volatile(
        "mma.sync.aligned.m16n8k16.row.col.f32.bf16.bf16.f32 "
        "{%0,%1,%2,%3}, {%4,%5,%6,%7}, {%8,%9}, {%0,%1,%2,%3};"
        : "+f"(c[0]), "+f"(c[1]), "+f"(c[2]), "+f"(c[3])
        : "r"(a[0]), "r"(a[1]), "r"(a[2]), "r"(a[3]), "r"(b0), "r"(b1));
}

// ===========================================================================
// WHT primitives
// ===========================================================================
__device__ __forceinline__ void wht64(float v[64]) {
#pragma unroll
    for (int s = 1; s < 64; s <<= 1) {
#pragma unroll
        for (int i = 0; i < 64; i++) {
            if ((i & s) == 0) {
                float a = v[i], b = v[i + s];
                v[i]     = a + b;
                v[i + s] = a - b;
            }
        }
    }
}

__global__ void init_kernel() {
    g_maxx_bits = 0;
    g_maxw_bits = 0;
}

// ---------------------------------------------------------------------------
// FUSED column-axis WHT-4096 (8 cols / 512 threads / 128 KB smem)
// ---------------------------------------------------------------------------
#define FSWZ(a) ((a) ^ ((((a) >> 9) & 3) << 3))

template <bool DO_MAX, bool FINAL>
__global__ __launch_bounds__(512) void colwht_fused8_kernel(const float* __restrict__ in,
                                                            float* __restrict__ out,
                                                            int ncols,
                                                            const float* __restrict__ bias) {
    extern __shared__ float sm[];
    int tid  = threadIdx.x;
    int col0 = blockIdx.x * 8;

#pragma unroll
    for (int j = 0; j < 16; j++) {
        int i = tid + j * 512;
        int r = i >> 1, q = i & 1;
        float4 v = *(const float4*)&in[(size_t)r * ncols + col0 + q * 4];
        *(float4*)&sm[FSWZ(r * 8 + q * 4)] = v;
    }
    __syncthreads();

    int g = tid >> 3, c = tid & 7;
    float v[64];

#pragma unroll
    for (int k = 0; k < 64; k++) v[k] = sm[FSWZ((g * 64 + k) * 8 + c)];
    wht64(v);
#pragma unroll
    for (int k = 0; k < 64; k++) sm[FSWZ((g * 64 + k) * 8 + c)] = v[k];
    __syncthreads();

#pragma unroll
    for (int k = 0; k < 64; k++) v[k] = sm[FSWZ((g + 64 * k) * 8 + c)];
    wht64(v);

    if (DO_MAX) {
        float m = 0.f;
#pragma unroll
        for (int k = 0; k < 64; k++) m = fmaxf(m, fabsf(v[k]));
#pragma unroll
        for (int off = 16; off; off >>= 1)
            m = fmaxf(m, __shfl_xor_sync(0xffffffffu, m, off));
        if ((tid & 31) == 0) atomicMax(&g_maxx_bits, __float_as_int(m));
    }

    float scale = 1.f, bv = 0.f;
    if (FINAL) {
        float mx = __int_as_float(g_maxx_bits);
        float mw = __int_as_float(g_maxw_bits);
        scale = (mx / 127.f) * (mw / 127.f) * 0x1p-24f;
        bv    = bias[col0 + c];
    }
#pragma unroll
    for (int k = 0; k < 64; k++) {
        size_t idx = (size_t)(g + 64 * k) * ncols + col0 + c;
        out[idx] = FINAL ? (v[k] * scale + bv) : v[k];
    }
}

// ---------------------------------------------------------------------------
// Row-axis WHT (contiguous dim 4096) with coalesced writeout
// ---------------------------------------------------------------------------
template <bool DO_MAXW>
__global__ __launch_bounds__(128) void rowwht_kernel(const float* __restrict__ in,
                                                     float* __restrict__ out) {
    __shared__ float sm[2][4096];
    int g   = threadIdx.x >> 6;
    int t   = threadIdx.x & 63;
    int row = blockIdx.x * 2 + g;

    float v[64];
#pragma unroll
    for (int k = 0; k < 64; k++) v[k] = in[(size_t)row * 4096 + t + (k << 6)];
    wht64(v);
#pragma unroll
    for (int k = 0; k < 64; k++) {
        int a = t + (k << 6);
        sm[g][a ^ ((a >> 6) & 31)] = v[k];
    }
    __syncthreads();
#pragma unroll
    for (int k = 0; k < 64; k++) {
        int a = (t << 6) + k;
        v[k] = sm[g][a ^ ((a >> 6) & 31)];
    }
    wht64(v);

    if (DO_MAXW) {
        float m = 0.f;
#pragma unroll
        for (int k = 0; k < 64; k++) m = fmaxf(m, fabsf(v[k]));
#pragma unroll
        for (int off = 16; off; off >>= 1)
            m = fmaxf(m, __shfl_xor_sync(0xffffffffu, m, off));
        if ((threadIdx.x & 31) == 0) atomicMax(&g_maxw_bits, __float_as_int(m));
    }

    __syncthreads();
#pragma unroll
    for (int k = 0; k < 64; k++) {
        int a = (t << 6) + k;
        sm[g][a ^ ((a >> 6) & 31)] = v[k];
    }
    __syncthreads();

    size_t base = (size_t)blockIdx.x * 2 * 4096;
#pragma unroll
    for (int i = 0; i < 64; i++) {
        int lin = threadIdx.x + i * 128;
        int gg  = lin >> 12;
        int a   = lin & 4095;
        out[base + lin] = sm[gg][a ^ ((a >> 6) & 31)];
    }
}

// ===========================================================================
// MERGED quantization kernel (one launch for both operands).
// blockIdx.y == 0 : elementwise x-quant (fp32 xr -> bf16 xq)
// blockIdx.y == 1 : w-quant + 32x32 transpose (fp32 wr -> bf16 wqT [F][IN])
// ===========================================================================
__device__ __forceinline__ float stoch_q(float xv, float nv, float s) {
    float xs = xv / s;
    float f  = floorf(xs);
    float q  = f + ((nv < xs - f) ? 1.f : 0.f);
    return fminf(127.f, fmaxf(-127.f, q));
}

__global__ __launch_bounds__(256) void quant_both_kernel(const float* __restrict__ xr,
                                                         const float* __restrict__ noise_x,
                                                         __nv_bfloat16* __restrict__ xq,
                                                         const float* __restrict__ wr,
                                                         const float* __restrict__ noise_w,
                                                         __nv_bfloat16* __restrict__ wqT) {
    if (blockIdx.y == 0) {
        // x path: 8192 blocks x 256 threads x 4 elems
        int i = blockIdx.x * 256 + threadIdx.x;
        float s = __int_as_float(g_maxx_bits) / 127.f;
        float4 x  = ((const float4*)xr)[i];
        float4 nz = ((const float4*)noise_x)[i];
        __nv_bfloat162 lo = __floats2bfloat162_rn(stoch_q(x.x, nz.x, s), stoch_q(x.y, nz.y, s));
        __nv_bfloat162 hi = __floats2bfloat162_rn(stoch_q(x.z, nz.z, s), stoch_q(x.w, nz.w, s));
        uint2 o;
        o.x = *(uint32_t*)&lo;
        o.y = *(uint32_t*)&hi;
        ((uint2*)xq)[i] = o;
    } else {
        // w path: 8192 blocks mapped to 128x64 tile grid of 32x32 transposes
        __shared__ __nv_bfloat16 t[32][33];
        float s = __int_as_float(g_maxw_bits) / 127.f;
        int bx = blockIdx.x & 127;   // F tile (128 tiles)
        int by = blockIdx.x >> 7;    // IN tile (64 tiles)
        int tx = threadIdx.x & 31;
        int ty = threadIdx.x >> 5;   // 0..7
        int x  = bx * 32 + tx;       // F index
        int y0 = by * 32;            // IN base
#pragma unroll
        for (int j = 0; j < 4; j++) {
            int y   = y0 + ty + j * 8;
            int idx = y * F_DIM + x;
            t[ty + j * 8][tx] = __float2bfloat16(stoch_q(wr[idx], noise_w[idx], s));
        }
        __syncthreads();
#pragma unroll
        for (int j = 0; j < 4; j++) {
            int fo = bx * 32 + ty + j * 8;
            wqT[(size_t)fo * IN_DIM + y0 + tx] = t[tx][ty + j * 8];
        }
    }
}

// ===========================================================================
// Pipelined bf16 GEMM (HMMA): CTA 128x128, 4 warps (2x2), warp tile 64x64,
// BK=64 (128B rows, SW), 3-stage cp.async, 2 CTAs/SM.
// LDSM:MMA ratio 8:32 (vs 6:8 before) — tests whether HMMA has issue headroom.
// ===========================================================================
#define GBM 128
#define GBN 128
#define GBK 64
#define NSTAGE 3
#define KT (IN_DIM / GBK)                          // 32
#define STAGE_BYTES ((GBM + GBN) * GBK * 2)        // 32768
#define GEMM_SMEM (NSTAGE * STAGE_BYTES)           // 98304

__global__ __launch_bounds__(128, 2) void gemm_bf16_kernel(const __nv_bfloat16* __restrict__ A,
                                                           const __nv_bfloat16* __restrict__ Bm,
                                                           float* __restrict__ C) {
    extern __shared__ char smem[];
    uint32_t sb = smem_u32(smem);
    int tid = threadIdx.x, warp = tid >> 5, lane = tid & 31;
    int bm = blockIdx.y * GBM, bn = blockIdx.x * GBN;
    int wm = (warp >> 1) * 64;   // 2 warps along M, tile 64
    int wn = (warp & 1) * 64;    // 2 warps along N, tile 64

    float acc[4][8][4];
#pragma unroll
    for (int i = 0; i < 4; i++)
#pragma unroll
        for (int j = 0; j < 8; j++)
#pragma unroll
            for (int k = 0; k < 4; k++) acc[i][j][k] = 0.f;

    auto load_stage = [&](int s, int ki) {
        uint32_t sA = sb + s * STAGE_BYTES;
        uint32_t sB = sA + GBM * GBK * 2;
        int k0 = ki * GBK;
#pragma unroll
        for (int j = 0; j < 8; j++) {      // A: 1024 chunks / 128 threads
            int c = tid + j * 128;
            int row = c >> 3, cc = c & 7;
            cpasync16(sA + swz(row * 128 + cc * 16),
                      A + (size_t)(bm + row) * IN_DIM + k0 + cc * 8);
        }
#pragma unroll
        for (int j = 0; j < 8; j++) {      // B: 1024 chunks
            int c = tid + j * 128;
            int row = c >> 3, cc = c & 7;
            cpasync16(sB + swz(row * 128 + cc * 16),
                      Bm + (size_t)(bn + row) * IN_DIM + k0 + cc * 8);
        }
        asm volatile("cp.async.commit_group;\n");
    };

    load_stage(0, 0);
    load_stage(1, 1);

    int rl = lane & 15, chh = (lane >> 4) * 16;
    int cur = 0;
    for (int i = 0; i < KT; i++) {
        asm volatile("cp.async.wait_group 1;\n");
        __syncthreads();
        if (i + 2 < KT) {
            int nxt = cur + 2; if (nxt >= NSTAGE) nxt -= NSTAGE;
            load_stage(nxt, i + 2);
        }

        uint32_t sA = sb + cur * STAGE_BYTES;
        uint32_t sB = sA + GBM * GBK * 2;
#pragma unroll
        for (int ks = 0; ks < 4; ks++) {
            uint32_t a[4][4], b[4][4];
#pragma unroll
            for (int mt = 0; mt < 4; mt++)
                ldsm_x4(a[mt], sA + swz((wm + mt * 16 + rl) * 128 + ks * 32 + chh));
#pragma unroll
            for (int ng = 0; ng < 4; ng++)
                ldsm_x4(b[ng], sB + swz((wn + ng * 16 + rl) * 128 + ks * 32 + chh));
#pragma unroll
            for (int mt = 0; mt < 4; mt++)
#pragma unroll
                for (int ng = 0; ng < 4; ng++) {
                    mma_bf16(acc[mt][2 * ng + 0], a[mt], b[ng][0], b[ng][2]);
                    mma_bf16(acc[mt][2 * ng + 1], a[mt], b[ng][1], b[ng][3]);
                }
        }
        cur = (cur + 1 == NSTAGE) ? 0 : cur + 1;
    }

    float* outp = C + (size_t)bm * F_DIM + bn;
#pragma unroll
    for (int mt = 0; mt < 4; mt++)
#pragma unroll
        for (int nt = 0; nt < 8; nt++) {
            int row = wm + mt * 16 + (lane >> 2);
            int col = wn + nt * 8 + (lane & 3) * 2;
            *(float2*)&outp[(size_t)row * F_DIM + col] =
                make_float2(acc[mt][nt][0], acc[mt][nt][1]);
            *(float2*)&outp[(size_t)(row + 8) * F_DIM + col] =
                make_float2(acc[mt][nt][2], acc[mt][nt][3]);
        }
}

// ===========================================================================
// Host launcher
// ===========================================================================
extern "C" void kernel_launch(void* const* d_in, const int* in_sizes, int n_in,
                              void* d_out, int out_size) {
    const float* x       = (const float*)d_in[0];  // [4096, 2048]
    const float* w       = (const float*)d_in[1];  // [2048, 4096]
    const float* bias    = (const float*)d_in[2];  // [4096]
    const float* noise_x = (const float*)d_in[5];  // [4096, 2048]
    const float* noise_w = (const float*)d_in[6];  // [2048, 4096]
    float* out = (float*)d_out;                    // [4096, 4096]

    float*         xr_p = nullptr;
    float*         wr_p = nullptr;
    __nv_bfloat16* xq_p = nullptr;
    __nv_bfloat16* wq_p = nullptr;
    float*         yr_p = nullptr;
    cudaGetSymbolAddress((void**)&xr_p, g_xr);
    cudaGetSymbolAddress((void**)&wr_p, g_wr);
    cudaGetSymbolAddress((void**)&xq_p, g_xq);
    cudaGetSymbolAddress((void**)&wq_p, g_wqT);
    cudaGetSymbolAddress((void**)&yr_p, g_yr);

    const int CW_SMEM = 4096 * 8 * sizeof(float);  // 128 KB
    cudaFuncSetAttribute(gemm_bf16_kernel, cudaFuncAttributeMaxDynamicSharedMemorySize,
                         GEMM_SMEM);
    cudaFuncSetAttribute(colwht_fused8_kernel<true, false>,
                         cudaFuncAttributeMaxDynamicSharedMemorySize, CW_SMEM);
    cudaFuncSetAttribute(colwht_fused8_kernel<false, true>,
                         cudaFuncAttributeMaxDynamicSharedMemorySize, CW_SMEM);

    init_kernel<<<1, 1>>>();

    // forward rotations (both maxes), then one merged quant launch
    colwht_fused8_kernel<true, false><<<IN_DIM / 8, 512, CW_SMEM>>>(x, xr_p, IN_DIM, nullptr);
    rowwht_kernel<true><<<IN_DIM / 2, 128>>>(w, wr_p);
    quant_both_kernel<<<dim3(8192, 2), 256>>>(xr_p, noise_x, xq_p, wr_p, noise_w, wq_p);

    // pipelined bf16 HMMA GEMM -> float (exact integer arithmetic)
    gemm_bf16_kernel<<<dim3(F_DIM / GBN, B_DIM / GBM), 128, GEMM_SMEM>>>(xq_p, wq_p, yr_p);

    // inverse rotations: rows, then fused column pair with scale+bias -> out
    rowwht_kernel<false><<<B_DIM / 2, 128>>>(yr_p, yr_p);
    colwht_fused8_kernel<false, true><<<F_DIM / 8, 512, CW_SMEM>>>(yr_p, out, F_DIM, bias);
}

// round 13
// speedup vs baseline: 1.0251x; 1.0251x over previous
#include <cuda_runtime.h>
#include <cuda_bf16.h>
#include <cstdint>

#define B_DIM 4096
#define IN_DIM 2048
#define F_DIM 4096

// ---------------------------------------------------------------------------
// Scratch (device globals: no allocation allowed)
// ---------------------------------------------------------------------------
__device__ float          g_xr[B_DIM * IN_DIM];    // rotated activations (fp32 — REQUIRED)
__device__ float          g_wr[IN_DIM * F_DIM];    // rotated weights (fp32 — REQUIRED)
__device__ __nv_bfloat16  g_xq[B_DIM * IN_DIM];    // quantized activations [M][K]
__device__ __nv_bfloat16  g_wqT[F_DIM * IN_DIM];   // quantized weights TRANSPOSED [N][K]
__device__ float          g_yr[B_DIM * F_DIM];     // GEMM result (float, exact ints)
__device__ int            g_maxx_bits;
__device__ int            g_maxw_bits;

// ===========================================================================
// Helpers
// ===========================================================================
__device__ __forceinline__ uint32_t smem_u32(const void* p) {
    uint32_t a;
    asm("{ .reg .u64 t; cvta.to.shared.u64 t, %1; cvt.u32.u64 %0, t; }" : "=r"(a) : "l"(p));
    return a;
}

__device__ __forceinline__ void cpasync16(uint32_t dst, const void* src) {
    asm volatile("cp.async.cg.shared.global [%0], [%1], 16;\n" :: "r"(dst), "l"(src));
}

// Swizzle<3,4,3>: XOR 16B-chunk bits [6:4] with 128B-line bits [9:7]
__device__ __forceinline__ uint32_t swz(uint32_t o) { return o ^ (((o >> 7) & 7) << 4); }

__device__ __forceinline__ void ldsm_x4(uint32_t r[4], uint32_t addr) {
    asm volatile("ldmatrix.sync.aligned.m8n8.x4.shared.b16 {%0,%1,%2,%3}, [%4];"
                 : "=r"(r[0]), "=r"(r[1]), "=r"(r[2]), "=r"(r[3]) : "r"(addr));
}

__device__ __forceinline__ void mma_bf16(float c[4], const uint32_t a[4], uint32_t b0, uint32_t b1) {
    asm volatile(
        "mma.sync.aligned.m16n8k16.row.col.f32.bf16.bf16.f32 "
        "{%0,%1,%2,%3}, {%4,%5,%6,%7}, {%8,%9}, {%0,%1,%2,%3};"
        : "+f"(c[0]), "+f"(c[1]), "+f"(c[2]), "+f"(c[3])
        : "r"(a[0]), "r"(a[1]), "r"(a[2]), "r"(a[3]), "r"(b0), "r"(b1));
}

// ===========================================================================
// WHT primitives
// ===========================================================================
__device__ __forceinline__ void wht64(float v[64]) {
#pragma unroll
    for (int s = 1; s < 64; s <<= 1) {
#pragma unroll
        for (int i = 0; i < 64; i++) {
            if ((i & s) == 0) {
                float a = v[i], b = v[i + s];
                v[i]     = a + b;
                v[i + s] = a - b;
            }
        }
    }
}

__global__ void init_kernel() {
    g_maxx_bits = 0;
    g_maxw_bits = 0;
}

// ---------------------------------------------------------------------------
// FUSED column-axis WHT-4096 (8 cols / 512 threads / 128 KB smem)
// ---------------------------------------------------------------------------
#define FSWZ(a) ((a) ^ ((((a) >> 9) & 3) << 3))

template <bool DO_MAX, bool FINAL>
__global__ __launch_bounds__(512) void colwht_fused8_kernel(const float* __restrict__ in,
                                                            float* __restrict__ out,
                                                            int ncols,
                                                            const float* __restrict__ bias) {
    extern __shared__ float sm[];
    int tid  = threadIdx.x;
    int col0 = blockIdx.x * 8;

#pragma unroll
    for (int j = 0; j < 16; j++) {
        int i = tid + j * 512;
        int r = i >> 1, q = i & 1;
        float4 v = *(const float4*)&in[(size_t)r * ncols + col0 + q * 4];
        *(float4*)&sm[FSWZ(r * 8 + q * 4)] = v;
    }
    __syncthreads();

    int g = tid >> 3, c = tid & 7;
    float v[64];

#pragma unroll
    for (int k = 0; k < 64; k++) v[k] = sm[FSWZ((g * 64 + k) * 8 + c)];
    wht64(v);
#pragma unroll
    for (int k = 0; k < 64; k++) sm[FSWZ((g * 64 + k) * 8 + c)] = v[k];
    __syncthreads();

#pragma unroll
    for (int k = 0; k < 64; k++) v[k] = sm[FSWZ((g + 64 * k) * 8 + c)];
    wht64(v);

    if (DO_MAX) {
        float m = 0.f;
#pragma unroll
        for (int k = 0; k < 64; k++) m = fmaxf(m, fabsf(v[k]));
#pragma unroll
        for (int off = 16; off; off >>= 1)
            m = fmaxf(m, __shfl_xor_sync(0xffffffffu, m, off));
        if ((tid & 31) == 0) atomicMax(&g_maxx_bits, __float_as_int(m));
    }

    float scale = 1.f, bv = 0.f;
    if (FINAL) {
        float mx = __int_as_float(g_maxx_bits);
        float mw = __int_as_float(g_maxw_bits);
        scale = (mx / 127.f) * (mw / 127.f) * 0x1p-24f;
        bv    = bias[col0 + c];
    }
#pragma unroll
    for (int k = 0; k < 64; k++) {
        size_t idx = (size_t)(g + 64 * k) * ncols + col0 + c;
        out[idx] = FINAL ? (v[k] * scale + bv) : v[k];
    }
}

// ---------------------------------------------------------------------------
// Row-axis WHT (contiguous dim 4096) with coalesced writeout
// ---------------------------------------------------------------------------
template <bool DO_MAXW>
__global__ __launch_bounds__(128) void rowwht_kernel(const float* __restrict__ in,
                                                     float* __restrict__ out) {
    __shared__ float sm[2][4096];
    int g   = threadIdx.x >> 6;
    int t   = threadIdx.x & 63;
    int row = blockIdx.x * 2 + g;

    float v[64];
#pragma unroll
    for (int k = 0; k < 64; k++) v[k] = in[(size_t)row * 4096 + t + (k << 6)];
    wht64(v);
#pragma unroll
    for (int k = 0; k < 64; k++) {
        int a = t + (k << 6);
        sm[g][a ^ ((a >> 6) & 31)] = v[k];
    }
    __syncthreads();
#pragma unroll
    for (int k = 0; k < 64; k++) {
        int a = (t << 6) + k;
        v[k] = sm[g][a ^ ((a >> 6) & 31)];
    }
    wht64(v);

    if (DO_MAXW) {
        float m = 0.f;
#pragma unroll
        for (int k = 0; k < 64; k++) m = fmaxf(m, fabsf(v[k]));
#pragma unroll
        for (int off = 16; off; off >>= 1)
            m = fmaxf(m, __shfl_xor_sync(0xffffffffu, m, off));
        if ((threadIdx.x & 31) == 0) atomicMax(&g_maxw_bits, __float_as_int(m));
    }

    __syncthreads();
#pragma unroll
    for (int k = 0; k < 64; k++) {
        int a = (t << 6) + k;
        sm[g][a ^ ((a >> 6) & 31)] = v[k];
    }
    __syncthreads();

    size_t base = (size_t)blockIdx.x * 2 * 4096;
#pragma unroll
    for (int i = 0; i < 64; i++) {
        int lin = threadIdx.x + i * 128;
        int gg  = lin >> 12;
        int a   = lin & 4095;
        out[base + lin] = sm[gg][a ^ ((a >> 6) & 31)];
    }
}

// ===========================================================================
// Quantization (fp32 in, bf16 integer-valued out)
// ===========================================================================
__device__ __forceinline__ float stoch_q(float xv, float nv, float s) {
    float xs = xv / s;
    float f  = floorf(xs);
    float q  = f + ((nv < xs - f) ? 1.f : 0.f);
    return fminf(127.f, fmaxf(-127.f, q));
}

__global__ __launch_bounds__(256) void quantx_kernel(const float* __restrict__ xr,
                                                     const float* __restrict__ noise,
                                                     __nv_bfloat16* __restrict__ qo,
                                                     int n4) {
    int i = blockIdx.x * blockDim.x + threadIdx.x;
    if (i >= n4) return;
    float s = __int_as_float(g_maxx_bits) / 127.f;
    float4 x  = ((const float4*)xr)[i];
    float4 nz = ((const float4*)noise)[i];
    __nv_bfloat162 lo = __floats2bfloat162_rn(stoch_q(x.x, nz.x, s), stoch_q(x.y, nz.y, s));
    __nv_bfloat162 hi = __floats2bfloat162_rn(stoch_q(x.z, nz.z, s), stoch_q(x.w, nz.w, s));
    uint2 o;
    o.x = *(uint32_t*)&lo;
    o.y = *(uint32_t*)&hi;
    ((uint2*)qo)[i] = o;
}

// weights: quantize + transpose [IN][F] -> [F][IN] bf16 (K-major B operand)
__global__ __launch_bounds__(256) void quantw_transpose_kernel(const float* __restrict__ wr,
                                                               const float* __restrict__ noise,
                                                               __nv_bfloat16* __restrict__ qoT) {
    __shared__ __nv_bfloat16 t[32][33];
    float s = __int_as_float(g_maxw_bits) / 127.f;
    int x  = blockIdx.x * 32 + threadIdx.x;   // F index
    int y0 = blockIdx.y * 32;                 // IN base
#pragma unroll
    for (int j = 0; j < 4; j++) {
        int y   = y0 + threadIdx.y + j * 8;
        int idx = y * F_DIM + x;
        t[threadIdx.y + j * 8][threadIdx.x] = __float2bfloat16(stoch_q(wr[idx], noise[idx], s));
    }
    __syncthreads();
#pragma unroll
    for (int j = 0; j < 4; j++) {
        int fo = blockIdx.x * 32 + threadIdx.y + j * 8;
        qoT[(size_t)fo * IN_DIM + y0 + threadIdx.x] = t[threadIdx.x][threadIdx.y + j * 8];
    }
}

// ===========================================================================
// Pipelined bf16 GEMM (HMMA), PROVEN config: CTA 128x128, 8 warps (2x4),
// warp tile 64x32, BK=64 (128B rows, SW), 3-stage cp.async, 2 CTAs/SM.
// ===========================================================================
#define GBM 128
#define GBN 128
#define GBK 64
#define NSTAGE 3
#define KT (IN_DIM / GBK)                          // 32
#define STAGE_BYTES ((GBM + GBN) * GBK * 2)        // 32768
#define GEMM_SMEM (NSTAGE * STAGE_BYTES)           // 98304

__global__ __launch_bounds__(256, 2) void gemm_bf16_kernel(const __nv_bfloat16* __restrict__ A,
                                                           const __nv_bfloat16* __restrict__ Bm,
                                                           float* __restrict__ C) {
    extern __shared__ char smem[];
    uint32_t sb = smem_u32(smem);
    int tid = threadIdx.x, warp = tid >> 5, lane = tid & 31;
    int bm = blockIdx.y * GBM, bn = blockIdx.x * GBN;
    int wm = (warp >> 2) * 64;   // 2 warps along M
    int wn = (warp & 3) * 32;    // 4 warps along N

    float acc[4][4][4];
#pragma unroll
    for (int i = 0; i < 4; i++)
#pragma unroll
        for (int j = 0; j < 4; j++)
#pragma unroll
            for (int k = 0; k < 4; k++) acc[i][j][k] = 0.f;

    auto load_stage = [&](int s, int ki) {
        uint32_t sA = sb + s * STAGE_BYTES;
        uint32_t sB = sA + GBM * GBK * 2;
        int k0 = ki * GBK;
#pragma unroll
        for (int j = 0; j < 4; j++) {
            int c = tid + j * 256;
            int row = c >> 3, cc = c & 7;
            cpasync16(sA + swz(row * 128 + cc * 16),
                      A + (size_t)(bm + row) * IN_DIM + k0 + cc * 8);
        }
#pragma unroll
        for (int j = 0; j < 4; j++) {
            int c = tid + j * 256;
            int row = c >> 3, cc = c & 7;
            cpasync16(sB + swz(row * 128 + cc * 16),
                      Bm + (size_t)(bn + row) * IN_DIM + k0 + cc * 8);
        }
        asm volatile("cp.async.commit_group;\n");
    };

    load_stage(0, 0);
    load_stage(1, 1);

    int rl = lane & 15, chh = (lane >> 4) * 16;
    int cur = 0;
    for (int i = 0; i < KT; i++) {
        asm volatile("cp.async.wait_group 1;\n");
        __syncthreads();
        if (i + 2 < KT) {
            int nxt = cur + 2; if (nxt >= NSTAGE) nxt -= NSTAGE;
            load_stage(nxt, i + 2);
        }

        uint32_t sA = sb + cur * STAGE_BYTES;
        uint32_t sB = sA + GBM * GBK * 2;
#pragma unroll
        for (int ks = 0; ks < 4; ks++) {
            uint32_t a[4][4], b[2][4];
#pragma unroll
            for (int mt = 0; mt < 4; mt++)
                ldsm_x4(a[mt], sA + swz((wm + mt * 16 + rl) * 128 + ks * 32 + chh));
#pragma unroll
            for (int ng = 0; ng < 2; ng++)
                ldsm_x4(b[ng], sB + swz((wn + ng * 16 + rl) * 128 + ks * 32 + chh));
#pragma unroll
            for (int mt = 0; mt < 4; mt++)
#pragma unroll
                for (int ng = 0; ng < 2; ng++) {
                    mma_bf16(acc[mt][2 * ng + 0], a[mt], b[ng][0], b[ng][2]);
                    mma_bf16(acc[mt][2 * ng + 1], a[mt], b[ng][1], b[ng][3]);
                }
        }
        cur = (cur + 1 == NSTAGE) ? 0 : cur + 1;
    }

    float* outp = C + (size_t)bm * F_DIM + bn;
#pragma unroll
    for (int mt = 0; mt < 4; mt++)
#pragma unroll
        for (int nt = 0; nt < 4; nt++) {
            int row = wm + mt * 16 + (lane >> 2);
            int col = wn + nt * 8 + (lane & 3) * 2;
            *(float2*)&outp[(size_t)row * F_DIM + col] =
                make_float2(acc[mt][nt][0], acc[mt][nt][1]);
            *(float2*)&outp[(size_t)(row + 8) * F_DIM + col] =
                make_float2(acc[mt][nt][2], acc[mt][nt][3]);
        }
}

// ===========================================================================
// Host launcher — fork-join stream capture: x-chain || w-chain, join at GEMM
// ===========================================================================
extern "C" void kernel_launch(void* const* d_in, const int* in_sizes, int n_in,
                              void* d_out, int out_size) {
    const float* x       = (const float*)d_in[0];  // [4096, 2048]
    const float* w       = (const float*)d_in[1];  // [2048, 4096]
    const float* bias    = (const float*)d_in[2];  // [4096]
    const float* noise_x = (const float*)d_in[5];  // [4096, 2048]
    const float* noise_w = (const float*)d_in[6];  // [2048, 4096]
    float* out = (float*)d_out;                    // [4096, 4096]

    float*         xr_p = nullptr;
    float*         wr_p = nullptr;
    __nv_bfloat16* xq_p = nullptr;
    __nv_bfloat16* wq_p = nullptr;
    float*         yr_p = nullptr;
    cudaGetSymbolAddress((void**)&xr_p, g_xr);
    cudaGetSymbolAddress((void**)&wr_p, g_wr);
    cudaGetSymbolAddress((void**)&xq_p, g_xq);
    cudaGetSymbolAddress((void**)&wq_p, g_wqT);
    cudaGetSymbolAddress((void**)&yr_p, g_yr);

    const int CW_SMEM = 4096 * 8 * sizeof(float);  // 128 KB
    cudaFuncSetAttribute(gemm_bf16_kernel, cudaFuncAttributeMaxDynamicSharedMemorySize,
                         GEMM_SMEM);
    cudaFuncSetAttribute(colwht_fused8_kernel<true, false>,
                         cudaFuncAttributeMaxDynamicSharedMemorySize, CW_SMEM);
    cudaFuncSetAttribute(colwht_fused8_kernel<false, true>,
                         cudaFuncAttributeMaxDynamicSharedMemorySize, CW_SMEM);

    // Fork-join: independent x-chain and w-chain overlap until the GEMM.
    cudaStream_t s1;
    cudaStreamCreateWithFlags(&s1, cudaStreamNonBlocking);
    cudaEvent_t e_fork, e_join;
    cudaEventCreateWithFlags(&e_fork, cudaEventDisableTiming);
    cudaEventCreateWithFlags(&e_join, cudaEventDisableTiming);

    init_kernel<<<1, 1>>>();                       // default stream
    cudaEventRecord(e_fork, 0);
    cudaStreamWaitEvent(s1, e_fork, 0);

    // x-chain (default stream): WHT_batch(x) + max -> quantx
    colwht_fused8_kernel<true, false><<<IN_DIM / 8, 512, CW_SMEM>>>(x, xr_p, IN_DIM, nullptr);
    quantx_kernel<<<(B_DIM * IN_DIM / 4 + 255) / 256, 256>>>(xr_p, noise_x, xq_p,
                                                             B_DIM * IN_DIM / 4);

    // w-chain (stream s1): WHT_features(w) + max -> quantw + transpose
    rowwht_kernel<true><<<IN_DIM / 2, 128, 0, s1>>>(w, wr_p);
    quantw_transpose_kernel<<<dim3(F_DIM / 32, IN_DIM / 32), dim3(32, 8), 0, s1>>>(wr_p, noise_w,
                                                                                   wq_p);
    cudaEventRecord(e_join, s1);
    cudaStreamWaitEvent(0, e_join, 0);

    // join: pipelined bf16 HMMA GEMM -> float (exact integer arithmetic)
    gemm_bf16_kernel<<<dim3(F_DIM / GBN, B_DIM / GBM), 256, GEMM_SMEM>>>(xq_p, wq_p, yr_p);

    // inverse rotations: rows, then fused column pair with scale+bias -> out
    rowwht_kernel<false><<<B_DIM / 2, 128>>>(yr_p, yr_p);
    colwht_fused8_kernel<false, true><<<F_DIM / 8, 512, CW_SMEM>>>(yr_p, out, F_DIM, bias);
}